// round 2
// baseline (speedup 1.0000x reference)
#include <cuda_runtime.h>
#include <math.h>

#define FMA2(d,a,b) asm("fma.rn.f32x2 %0, %1, %2, %0;" : "+l"(d) : "l"(a), "l"(b))
typedef unsigned long long ull;

namespace {
constexpr int THREADS = 256;
constexpr int TB   = 64;     // batch samples per CTA (32 f32x2 pairs)
constexpr int XSTR = 33;     // padded pair stride
constexpr int NTCOL = 179;   // total t-table columns
constexpr size_t OFF_X = 0;
constexpr size_t OFF_T = (size_t)480 * XSTR * 8;             // 126720
constexpr size_t OFF_W = OFF_T + (size_t)NTCOL * XSTR * 8;   // 173976
constexpr size_t SMEM_BYTES = OFF_W + (size_t)128 * 32 * 8;  // 206744
}

// ---------------------------------------------------------------------------
// CG coefficients: computed on-device in fp64, exactly per reference convention
// ---------------------------------------------------------------------------
__device__ float g_cg[615];

// (l1, l2, l3, storage offset) for the 15 paths' CG tensors
__constant__ int4 c_combos[15] = {
    {0,0,0,  0}, {1,1,0,  1}, {2,2,0, 10}, {0,1,1, 35}, {1,0,1, 44},
    {1,1,1, 53}, {1,2,1, 80}, {2,1,1,125}, {2,2,1,170}, {0,2,2,245},
    {1,1,2,270}, {1,2,2,315}, {2,0,2,390}, {2,1,2,415}, {2,2,2,490}
};

struct cplx { double re, im; };

__device__ __forceinline__ double dfact(int n) {
    const double f[8] = {1.,1.,2.,6.,24.,120.,720.,5040.};
    return f[n];
}

__device__ double su2cg(int j1,int j2,int j3,int m1,int m2,int m3) {
    if (m1 + m2 != m3) return 0.0;
    double pref = (2.0*j3+1.0) * dfact(j1+j2-j3) * dfact(j1-j2+j3) *
                  dfact(-j1+j2+j3) / dfact(j1+j2+j3+1);
    pref = sqrt(pref);
    pref *= sqrt(dfact(j3+m3)*dfact(j3-m3)*dfact(j1-m1)*dfact(j1+m1)*
                 dfact(j2-m2)*dfact(j2+m2));
    double s = 0.0;
    for (int v = 0; v <= j1+j2-j3; ++v) {
        int a=j1+j2-j3-v, b=j1-m1-v, c=j2+m2-v, d=j3-j2+m1+v, e=j3-j1-m2+v;
        if (a<0||b<0||c<0||d<0||e<0) continue;
        double t = 1.0/(dfact(v)*dfact(a)*dfact(b)*dfact(c)*dfact(d)*dfact(e));
        s += (v & 1) ? -t : t;
    }
    return pref * s;
}

// entry (r,c) of q(l) (real->complex change of basis), including (-i)^l phase
__device__ cplx qent(int l, int r, int c) {
    const double isq = 0.70710678118654752440;
    int m = r - l;
    double re = 0.0, im = 0.0;
    if (m < 0) {
        if (c == l - m)      re = isq;
        else if (c == l + m) im = -isq;
    } else if (m == 0) {
        if (c == l) re = 1.0;
    } else {
        double sgn = (m & 1) ? -1.0 : 1.0;
        if (c == l + m)      re = sgn * isq;
        else if (c == l - m) im = sgn * isq;
    }
    int ph = l & 3;   // multiply by (-i)^l
    cplx o;
    if (ph == 0)      { o.re =  re; o.im =  im; }
    else if (ph == 1) { o.re =  im; o.im = -re; }
    else if (ph == 2) { o.re = -re; o.im = -im; }
    else              { o.re = -im; o.im =  re; }
    return o;
}

__global__ void cg_init_kernel() {
    __shared__ double csu2[125];
    int4 cmb = c_combos[blockIdx.x];
    const int l1 = cmb.x, l2 = cmb.y, l3 = cmb.z, off = cmb.w;
    const int n1 = 2*l1+1, n2 = 2*l2+1, n3 = 2*l3+1;
    const int tot = n1 * n2 * n3;
    for (int idx = threadIdx.x; idx < tot; idx += blockDim.x) {
        int i = idx / (n2*n3); int r = idx - i*n2*n3;
        int k = r / n3;        int n = r - k*n3;
        csu2[idx] = su2cg(l1, l2, l3, i-l1, k-l2, n-l3);
    }
    __syncthreads();
    // real_cg[a,b,c] = Re( sum_{i,k,n} Q1[i,a] Q2[k,b] conj(Q3[n,c]) Csu2[i,k,n] )
    for (int idx = threadIdx.x; idx < tot; idx += blockDim.x) {
        int a = idx / (n2*n3); int r = idx - a*n2*n3;
        int b = r / n3;        int c = r - b*n3;
        double acc = 0.0;
        for (int i = 0; i < n1; ++i) {
            cplx q1 = qent(l1, i, a);
            if (q1.re == 0.0 && q1.im == 0.0) continue;
            for (int k = 0; k < n2; ++k) {
                cplx q2 = qent(l2, k, b);
                if (q2.re == 0.0 && q2.im == 0.0) continue;
                double pr = q1.re*q2.re - q1.im*q2.im;
                double pi = q1.re*q2.im + q1.im*q2.re;
                for (int n = 0; n < n3; ++n) {
                    double cv = csu2[(i*n2 + k)*n3 + n];
                    if (cv == 0.0) continue;
                    cplx q3 = qent(l3, n, c);
                    acc += cv * (pr*q3.re + pi*q3.im);
                }
            }
        }
        g_cg[off + idx] = (float)acc;
    }
}

// ---------------------------------------------------------------------------
// t-table path descriptors (for the CG*y per-sample coefficients)
// ---------------------------------------------------------------------------
struct TP { int d1, d2, dk, yoff, tcol, cgoff; float norm; };
#define N0 0.06681531047810609f
#define N1 0.05103103630798288f
#define N2 0.05330017908890260f
__constant__ TP c_tp[15] = {
    {1,1,1,0,  0,  0, N0}, {3,3,1,1,  1,  1, N0}, {5,5,1,4,  4, 10, N0},
    {1,3,3,1,  9, 35, N1}, {3,1,3,0, 12, 44, N1}, {3,3,3,1, 21, 53, N1},
    {3,5,3,4, 30, 80, N1}, {5,3,3,1, 39,125, N1}, {5,5,3,4, 54,170, N1},
    {1,5,5,4, 69,245, N2}, {3,3,5,1, 74,270, N2}, {3,5,5,4, 89,315, N2},
    {5,1,5,0,104,390, N2}, {5,3,5,1,129,415, N2}, {5,5,5,4,154,490, N2}
};

// ---------------------------------------------------------------------------
// Main fused kernel
// ---------------------------------------------------------------------------
template<int D1, int K, int DK>
__device__ __forceinline__ void path_gemm(
    const float* __restrict__ W, int ldw, int wrow, int chunk,
    int xbase, int tcol,
    const float2* sh_x, const float2* sh_t, float2* sh_w,
    int tid, int lane, int warp, ull (&oacc)[4][5])
{
    __syncthreads();  // protect sh_w reuse
    for (int idx = tid; idx < K * 32; idx += THREADS) {
        int u = idx >> 5, c = idx & 31;
        float w = W[(wrow + u) * ldw + chunk * 32 + c];
        sh_w[idx] = make_float2(w, w);   // duplicated for f32x2
    }
    __syncthreads();
    ull A[4][D1];
#pragma unroll
    for (int c = 0; c < 4; ++c)
#pragma unroll
        for (int i = 0; i < D1; ++i) A[c][i] = 0ull;
    const int c0 = warp * 4;
    const float2* xp = sh_x + (size_t)xbase * XSTR + lane;
    const float2* wp = sh_w + c0;
#pragma unroll 4
    for (int u = 0; u < K; ++u) {
        ull xv[D1];
#pragma unroll
        for (int i = 0; i < D1; ++i)
            xv[i] = *reinterpret_cast<const ull*>(xp + (u * D1 + i) * XSTR);
#pragma unroll
        for (int c = 0; c < 4; ++c) {
            ull wv = *reinterpret_cast<const ull*>(wp + u * 32 + c);
#pragma unroll
            for (int i = 0; i < D1; ++i) FMA2(A[c][i], xv[i], wv);
        }
    }
    // fold A into output accumulators via t: oacc[c][k] += sum_i A[c][i]*t[i][k]
    const float2* tpt = sh_t + (size_t)tcol * XSTR + lane;
#pragma unroll
    for (int i = 0; i < D1; ++i)
#pragma unroll
        for (int k = 0; k < DK; ++k) {
            ull tv = *reinterpret_cast<const ull*>(tpt + (i * DK + k) * XSTR);
#pragma unroll
            for (int c = 0; c < 4; ++c) FMA2(oacc[c][k], A[c][i], tv);
        }
}

template<int DK>
__device__ __forceinline__ void store_chunk(
    float* __restrict__ out, long b0, int l3base, int chunk,
    int lane, int warp, ull (&oacc)[4][5])
{
    float buf[2][4 * DK];
#pragma unroll
    for (int c = 0; c < 4; ++c)
#pragma unroll
        for (int k = 0; k < DK; ++k) {
            float2 v = *reinterpret_cast<float2*>(&oacc[c][k]);
            buf[0][c * DK + k] = v.x;
            buf[1][c * DK + k] = v.y;
        }
    int col0 = l3base + (chunk * 32 + warp * 4) * DK;
#pragma unroll
    for (int h = 0; h < 2; ++h) {
        float* o = out + (b0 + 2 * lane + h) * 480 + col0;
#pragma unroll
        for (int q = 0; q < DK; ++q)
            reinterpret_cast<float4*>(o)[q] =
                make_float4(buf[h][4*q], buf[h][4*q+1], buf[h][4*q+2], buf[h][4*q+3]);
    }
}

__device__ __forceinline__ void zero_acc(ull (&oacc)[4][5]) {
#pragma unroll
    for (int c = 0; c < 4; ++c)
#pragma unroll
        for (int k = 0; k < 5; ++k) oacc[c][k] = 0ull;
}

__global__ void __launch_bounds__(THREADS, 1)
tpl_kernel(const float* __restrict__ x, const float* __restrict__ y,
           const float* __restrict__ W0, const float* __restrict__ W1,
           const float* __restrict__ W2, float* __restrict__ out)
{
    extern __shared__ unsigned char smem[];
    float2* sh_x = reinterpret_cast<float2*>(smem + OFF_X);
    float2* sh_t = reinterpret_cast<float2*>(smem + OFF_T);
    float2* sh_w = reinterpret_cast<float2*>(smem + OFF_W);
    const int tid = threadIdx.x, lane = tid & 31, warp = tid >> 5;
    const long b0 = (long)blockIdx.x * TB;

    // ---- stage x transposed: sh_x[col][pair] as f32x2 over sample pairs ----
    for (int idx = tid; idx < TB * 120; idx += THREADS) {
        int s = idx / 120, q = idx - s * 120;
        float4 v = reinterpret_cast<const float4*>(x + (b0 + s) * 480)[q];
        int p = s >> 1, h = s & 1, c = 4 * q;
        float* bx = reinterpret_cast<float*>(sh_x);
        bx[((c+0)*XSTR+p)*2+h] = v.x;
        bx[((c+1)*XSTR+p)*2+h] = v.y;
        bx[((c+2)*XSTR+p)*2+h] = v.z;
        bx[((c+3)*XSTR+p)*2+h] = v.w;
    }
    // ---- stage y into sh_w scratch (overwritten by first W stage later) ----
    float* shy = reinterpret_cast<float*>(sh_w);
    for (int idx = tid; idx < TB * 9; idx += THREADS) {
        int s = idx / 9, j = idx - s * 9;
        shy[(j * 32 + (s >> 1)) * 2 + (s & 1)] = y[(b0 + s) * 9 + j];
    }
    __syncthreads();
    // ---- t tables: t_p[i,k][pair] = norm * sum_j cg[i,j,k] * y[pair][yoff+j]
    for (int p = 0; p < 15; ++p) {
        TP tp = c_tp[p];
        int n = tp.d1 * tp.dk * 32;
        for (int idx = tid; idx < n; idx += THREADS) {
            int pr = idx & 31, e = idx >> 5;
            int i = e / tp.dk, k = e - i * tp.dk;
            float ax = 0.f, ay = 0.f;
            for (int j = 0; j < tp.d2; ++j) {
                float cg = g_cg[tp.cgoff + (i * tp.d2 + j) * tp.dk + k];
                ax += cg * shy[((tp.yoff + j) * 32 + pr) * 2 + 0];
                ay += cg * shy[((tp.yoff + j) * 32 + pr) * 2 + 1];
            }
            sh_t[(tp.tcol + e) * XSTR + pr] = make_float2(ax * tp.norm, ay * tp.norm);
        }
    }
    // (path_gemm entry __syncthreads covers sh_t/sh_x visibility & sh_w reuse)

    ull oacc[4][5];
    // ---- l3 = 0: NV=128, DK=1, 4 column-chunks ----
    for (int ch = 0; ch < 4; ++ch) {
        zero_acc(oacc);
        path_gemm<1,128,1>(W0,128,  0,ch,  0,  0, sh_x,sh_t,sh_w,tid,lane,warp,oacc);
        path_gemm<3, 64,1>(W0,128,128,ch,128,  1, sh_x,sh_t,sh_w,tid,lane,warp,oacc);
        path_gemm<5, 32,1>(W0,128,192,ch,320,  4, sh_x,sh_t,sh_w,tid,lane,warp,oacc);
        store_chunk<1>(out,b0,  0,ch,lane,warp,oacc);
    }
    // ---- l3 = 1: NV=64, DK=3, 2 column-chunks ----
    for (int ch = 0; ch < 2; ++ch) {
        zero_acc(oacc);
        path_gemm<1,128,3>(W1,64,  0,ch,  0,  9, sh_x,sh_t,sh_w,tid,lane,warp,oacc);
        path_gemm<3, 64,3>(W1,64,128,ch,128, 12, sh_x,sh_t,sh_w,tid,lane,warp,oacc);
        path_gemm<3, 64,3>(W1,64,192,ch,128, 21, sh_x,sh_t,sh_w,tid,lane,warp,oacc);
        path_gemm<3, 64,3>(W1,64,256,ch,128, 30, sh_x,sh_t,sh_w,tid,lane,warp,oacc);
        path_gemm<5, 32,3>(W1,64,320,ch,320, 39, sh_x,sh_t,sh_w,tid,lane,warp,oacc);
        path_gemm<5, 32,3>(W1,64,352,ch,320, 54, sh_x,sh_t,sh_w,tid,lane,warp,oacc);
        store_chunk<3>(out,b0,128,ch,lane,warp,oacc);
    }
    // ---- l3 = 2: NV=32, DK=5, 1 column-chunk ----
    {
        zero_acc(oacc);
        path_gemm<1,128,5>(W2,32,  0,0,  0, 69, sh_x,sh_t,sh_w,tid,lane,warp,oacc);
        path_gemm<3, 64,5>(W2,32,128,0,128, 74, sh_x,sh_t,sh_w,tid,lane,warp,oacc);
        path_gemm<3, 64,5>(W2,32,192,0,128, 89, sh_x,sh_t,sh_w,tid,lane,warp,oacc);
        path_gemm<5, 32,5>(W2,32,256,0,320,104, sh_x,sh_t,sh_w,tid,lane,warp,oacc);
        path_gemm<5, 32,5>(W2,32,288,0,320,129, sh_x,sh_t,sh_w,tid,lane,warp,oacc);
        path_gemm<5, 32,5>(W2,32,320,0,320,154, sh_x,sh_t,sh_w,tid,lane,warp,oacc);
        store_chunk<5>(out,b0,320,0,lane,warp,oacc);
    }
}

// ---------------------------------------------------------------------------
extern "C" void kernel_launch(void* const* d_in, const int* in_sizes, int n_in,
                              void* d_out, int out_size) {
    const float* x  = (const float*)d_in[0];
    const float* y  = (const float*)d_in[1];
    const float* W0 = (const float*)d_in[2];
    const float* W1 = (const float*)d_in[3];
    const float* W2 = (const float*)d_in[4];
    float* out = (float*)d_out;

    cudaFuncSetAttribute(tpl_kernel,
                         cudaFuncAttributeMaxDynamicSharedMemorySize,
                         (int)SMEM_BYTES);
    cg_init_kernel<<<15, 128>>>();
    tpl_kernel<<<16384 / TB, THREADS, SMEM_BYTES>>>(x, y, W0, W1, W2, out);
}

// round 3
// speedup vs baseline: 1.5411x; 1.5411x over previous
#include <cuda_runtime.h>
#include <math.h>

#define FMA2(d,a,b) asm("fma.rn.f32x2 %0, %1, %2, %0;" : "+l"(d) : "l"(a), "l"(b))
typedef unsigned long long ull;

namespace {
constexpr int THREADS = 256;
constexpr int TB   = 64;     // batch samples per CTA (32 f32x2 pairs)
constexpr int XSTR = 33;     // padded pair stride (x/t tables)
constexpr int NTCOL = 179;   // total t-table columns
constexpr size_t OFF_X = 0;
constexpr size_t OFF_T = (size_t)480 * XSTR * 8;                 // 126720
constexpr size_t OFF_W = ((OFF_T + (size_t)NTCOL * XSTR * 8 + 15) / 16) * 16; // 173984 (16B aligned)
constexpr size_t SMEM_BYTES = OFF_W + 64 * 640;                  // + 40960 = 214944
}

// ---------------------------------------------------------------------------
// CG coefficients: computed on-device in fp64, exactly per reference convention
// ---------------------------------------------------------------------------
__device__ float g_cg[615];

__constant__ int4 c_combos[15] = {
    {0,0,0,  0}, {1,1,0,  1}, {2,2,0, 10}, {0,1,1, 35}, {1,0,1, 44},
    {1,1,1, 53}, {1,2,1, 80}, {2,1,1,125}, {2,2,1,170}, {0,2,2,245},
    {1,1,2,270}, {1,2,2,315}, {2,0,2,390}, {2,1,2,415}, {2,2,2,490}
};

struct cplx { double re, im; };

__device__ __forceinline__ double dfact(int n) {
    const double f[8] = {1.,1.,2.,6.,24.,120.,720.,5040.};
    return f[n];
}

__device__ double su2cg(int j1,int j2,int j3,int m1,int m2,int m3) {
    if (m1 + m2 != m3) return 0.0;
    double pref = (2.0*j3+1.0) * dfact(j1+j2-j3) * dfact(j1-j2+j3) *
                  dfact(-j1+j2+j3) / dfact(j1+j2+j3+1);
    pref = sqrt(pref);
    pref *= sqrt(dfact(j3+m3)*dfact(j3-m3)*dfact(j1-m1)*dfact(j1+m1)*
                 dfact(j2-m2)*dfact(j2+m2));
    double s = 0.0;
    for (int v = 0; v <= j1+j2-j3; ++v) {
        int a=j1+j2-j3-v, b=j1-m1-v, c=j2+m2-v, d=j3-j2+m1+v, e=j3-j1-m2+v;
        if (a<0||b<0||c<0||d<0||e<0) continue;
        double t = 1.0/(dfact(v)*dfact(a)*dfact(b)*dfact(c)*dfact(d)*dfact(e));
        s += (v & 1) ? -t : t;
    }
    return pref * s;
}

__device__ cplx qent(int l, int r, int c) {
    const double isq = 0.70710678118654752440;
    int m = r - l;
    double re = 0.0, im = 0.0;
    if (m < 0) {
        if (c == l - m)      re = isq;
        else if (c == l + m) im = -isq;
    } else if (m == 0) {
        if (c == l) re = 1.0;
    } else {
        double sgn = (m & 1) ? -1.0 : 1.0;
        if (c == l + m)      re = sgn * isq;
        else if (c == l - m) im = sgn * isq;
    }
    int ph = l & 3;   // multiply by (-i)^l
    cplx o;
    if (ph == 0)      { o.re =  re; o.im =  im; }
    else if (ph == 1) { o.re =  im; o.im = -re; }
    else if (ph == 2) { o.re = -re; o.im = -im; }
    else              { o.re = -im; o.im =  re; }
    return o;
}

__global__ void cg_init_kernel() {
    __shared__ double csu2[125];
    int4 cmb = c_combos[blockIdx.x];
    const int l1 = cmb.x, l2 = cmb.y, l3 = cmb.z, off = cmb.w;
    const int n1 = 2*l1+1, n2 = 2*l2+1, n3 = 2*l3+1;
    const int tot = n1 * n2 * n3;
    for (int idx = threadIdx.x; idx < tot; idx += blockDim.x) {
        int i = idx / (n2*n3); int r = idx - i*n2*n3;
        int k = r / n3;        int n = r - k*n3;
        csu2[idx] = su2cg(l1, l2, l3, i-l1, k-l2, n-l3);
    }
    __syncthreads();
    for (int idx = threadIdx.x; idx < tot; idx += blockDim.x) {
        int a = idx / (n2*n3); int r = idx - a*n2*n3;
        int b = r / n3;        int c = r - b*n3;
        double acc = 0.0;
        for (int i = 0; i < n1; ++i) {
            cplx q1 = qent(l1, i, a);
            if (q1.re == 0.0 && q1.im == 0.0) continue;
            for (int k = 0; k < n2; ++k) {
                cplx q2 = qent(l2, k, b);
                if (q2.re == 0.0 && q2.im == 0.0) continue;
                double pr = q1.re*q2.re - q1.im*q2.im;
                double pi = q1.re*q2.im + q1.im*q2.re;
                for (int n = 0; n < n3; ++n) {
                    double cv = csu2[(i*n2 + k)*n3 + n];
                    if (cv == 0.0) continue;
                    cplx q3 = qent(l3, n, c);
                    acc += cv * (pr*q3.re + pi*q3.im);
                }
            }
        }
        g_cg[off + idx] = (float)acc;
    }
}

// ---------------------------------------------------------------------------
// t-table path descriptors
// ---------------------------------------------------------------------------
struct TP { int d1, d2, dk, yoff, tcol, cgoff; float norm; };
#define N0 0.06681531047810609f
#define N1 0.05103103630798288f
#define N2 0.05330017908890260f
__constant__ TP c_tp[15] = {
    {1,1,1,0,  0,  0, N0}, {3,3,1,1,  1,  1, N0}, {5,5,1,4,  4, 10, N0},
    {1,3,3,1,  9, 35, N1}, {3,1,3,0, 12, 44, N1}, {3,3,3,1, 21, 53, N1},
    {3,5,3,4, 30, 80, N1}, {5,3,3,1, 39,125, N1}, {5,5,3,4, 54,170, N1},
    {1,5,5,4, 69,245, N2}, {3,3,5,1, 74,270, N2}, {3,5,5,4, 89,315, N2},
    {5,1,5,0,104,390, N2}, {5,3,5,1,129,415, N2}, {5,5,5,4,154,490, N2}
};

// ---------------------------------------------------------------------------
// Main fused kernel
//   warp layout: pair = warp*4 + (lane>>3)  (4 batch-pairs / warp, 8-lane x bcast)
//                g    = lane & 7            (column group; CT cols per thread)
// ---------------------------------------------------------------------------
template<int D1, int K, int DK, int CT>
__device__ __forceinline__ void path_gemm(
    const float* __restrict__ W, int ldw, int wrow, int colbase,
    int xbase, int tcol,
    const float* sh_xf, const float* sh_tf, char* sh_wb,
    int tid, int pair, int g, ull (&oacc)[8][5])
{
    constexpr int CW   = CT * 8;                 // cols per chunk
    constexpr int GS   = (CT == 8) ? 80 : 48;    // group stride (bytes, bank-spread)
    constexpr int UROW = 8 * GS;                 // per-u row stride (bytes)
    constexpr int KT   = (K > 64) ? 64 : K;

    ull acc[CT][D1];
#pragma unroll
    for (int c = 0; c < CT; ++c)
#pragma unroll
        for (int i = 0; i < D1; ++i) acc[c][i] = 0ull;

    const char* wgp = sh_wb + g * GS;

    for (int ks = 0; ks < K / KT; ++ks) {
        __syncthreads();   // previous readers of sh_w done
        for (int idx = tid; idx < KT * CW; idx += THREADS) {
            int u  = idx / CW, c = idx - u * CW;
            int gg = c / CT,  cc = c - gg * CT;
            float w = W[(wrow + ks * KT + u) * ldw + colbase + c];
            *reinterpret_cast<float2*>(sh_wb + u * UROW + gg * GS + cc * 8) =
                make_float2(w, w);
        }
        __syncthreads();

#pragma unroll 2
        for (int u = 0; u < KT; ++u) {
            const int ug = ks * KT + u;
            ull xv[D1];
#pragma unroll
            for (int i = 0; i < D1; ++i)
                xv[i] = *reinterpret_cast<const ull*>(
                    sh_xf + ((size_t)(xbase + ug * D1 + i) * XSTR + pair) * 2);
            ull wv[CT];
#pragma unroll
            for (int h = 0; h < CT / 2; ++h) {
                ulonglong2 lw = *reinterpret_cast<const ulonglong2*>(
                    wgp + u * UROW + h * 16);
                wv[2*h] = lw.x; wv[2*h+1] = lw.y;
            }
#pragma unroll
            for (int c = 0; c < CT; ++c)
#pragma unroll
                for (int i = 0; i < D1; ++i) FMA2(acc[c][i], xv[i], wv[c]);
        }
    }
    // fold A into outputs via per-sample t: oacc[c][k] += sum_i acc[c][i]*t[i][k]
#pragma unroll
    for (int i = 0; i < D1; ++i)
#pragma unroll
        for (int k = 0; k < DK; ++k) {
            ull tv = *reinterpret_cast<const ull*>(
                sh_tf + ((size_t)(tcol + i * DK + k) * XSTR + pair) * 2);
#pragma unroll
            for (int c = 0; c < CT; ++c) FMA2(oacc[c][k], acc[c][i], tv);
        }
}

template<int DK, int CT>
__device__ __forceinline__ void store_chunk(
    float* __restrict__ out, long b0, int l3base, int colbase,
    int pair, int g, ull (&oacc)[8][5])
{
    float buf[2][CT * DK];
#pragma unroll
    for (int c = 0; c < CT; ++c)
#pragma unroll
        for (int k = 0; k < DK; ++k) {
            float2 v = *reinterpret_cast<float2*>(&oacc[c][k]);
            buf[0][c * DK + k] = v.x;
            buf[1][c * DK + k] = v.y;
        }
    int col0 = l3base + (colbase + g * CT) * DK;
#pragma unroll
    for (int h = 0; h < 2; ++h) {
        float4* o = reinterpret_cast<float4*>(out + (b0 + 2 * pair + h) * 480 + col0);
#pragma unroll
        for (int q = 0; q < CT * DK / 4; ++q)
            o[q] = make_float4(buf[h][4*q], buf[h][4*q+1], buf[h][4*q+2], buf[h][4*q+3]);
    }
}

__device__ __forceinline__ void zero_acc(ull (&oacc)[8][5]) {
#pragma unroll
    for (int c = 0; c < 8; ++c)
#pragma unroll
        for (int k = 0; k < 5; ++k) oacc[c][k] = 0ull;
}

__global__ void __launch_bounds__(THREADS, 1)
tpl_kernel(const float* __restrict__ x, const float* __restrict__ y,
           const float* __restrict__ W0, const float* __restrict__ W1,
           const float* __restrict__ W2, float* __restrict__ out)
{
    extern __shared__ unsigned char smem[];
    float* sh_xf = reinterpret_cast<float*>(smem + OFF_X);
    float* sh_tf = reinterpret_cast<float*>(smem + OFF_T);
    char*  sh_wb = reinterpret_cast<char*>(smem + OFF_W);
    const int tid  = threadIdx.x;
    const int lane = tid & 31, warp = tid >> 5;
    const int pair = warp * 4 + (lane >> 3);
    const int g    = lane & 7;
    const long b0  = (long)blockIdx.x * TB;

    // ---- stage x transposed: sh_x[col][pair] packed f32x2 over sample pairs
    for (int idx = tid; idx < TB * 120; idx += THREADS) {
        int s = idx / 120, q = idx - s * 120;
        float4 v = reinterpret_cast<const float4*>(x + (b0 + s) * 480)[q];
        int p = s >> 1, h = s & 1, c = 4 * q;
        sh_xf[((c+0)*XSTR+p)*2+h] = v.x;
        sh_xf[((c+1)*XSTR+p)*2+h] = v.y;
        sh_xf[((c+2)*XSTR+p)*2+h] = v.z;
        sh_xf[((c+3)*XSTR+p)*2+h] = v.w;
    }
    // ---- stage y into sh_w scratch (overwritten by first W stage later) ----
    float* shy = reinterpret_cast<float*>(sh_wb);
    for (int idx = tid; idx < TB * 9; idx += THREADS) {
        int s = idx / 9, j = idx - s * 9;
        shy[(j * 32 + (s >> 1)) * 2 + (s & 1)] = y[(b0 + s) * 9 + j];
    }
    __syncthreads();
    // ---- t tables: t_p[i,k][pair] = norm * sum_j cg[i,j,k] * y[pair][yoff+j]
    for (int p = 0; p < 15; ++p) {
        TP tp = c_tp[p];
        int n = tp.d1 * tp.dk * 32;
        for (int idx = tid; idx < n; idx += THREADS) {
            int pr = idx & 31, e = idx >> 5;
            int i = e / tp.dk, k = e - i * tp.dk;
            float ax = 0.f, ay = 0.f;
            for (int j = 0; j < tp.d2; ++j) {
                float cg = g_cg[tp.cgoff + (i * tp.d2 + j) * tp.dk + k];
                ax += cg * shy[((tp.yoff + j) * 32 + pr) * 2 + 0];
                ay += cg * shy[((tp.yoff + j) * 32 + pr) * 2 + 1];
            }
            sh_tf[((size_t)(tp.tcol + e) * XSTR + pr) * 2 + 0] = ax * tp.norm;
            sh_tf[((size_t)(tp.tcol + e) * XSTR + pr) * 2 + 1] = ay * tp.norm;
        }
    }
    // (path_gemm's stage syncs publish sh_t/sh_x before first use of sh_w data)

    ull oacc[8][5];
    // ---- l3 = 0: 128 cols, DK=1, CT=8, 2 chunks of 64 ----
    for (int ch = 0; ch < 2; ++ch) {
        zero_acc(oacc);
        path_gemm<1,128,1,8>(W0,128,  0,ch*64,  0,  0, sh_xf,sh_tf,sh_wb,tid,pair,g,oacc);
        path_gemm<3, 64,1,8>(W0,128,128,ch*64,128,  1, sh_xf,sh_tf,sh_wb,tid,pair,g,oacc);
        path_gemm<5, 32,1,8>(W0,128,192,ch*64,320,  4, sh_xf,sh_tf,sh_wb,tid,pair,g,oacc);
        store_chunk<1,8>(out,b0,  0,ch*64,pair,g,oacc);
    }
    // ---- l3 = 1: 64 cols, DK=3, CT=8, 1 chunk ----
    {
        zero_acc(oacc);
        path_gemm<1,128,3,8>(W1,64,  0,0,  0,  9, sh_xf,sh_tf,sh_wb,tid,pair,g,oacc);
        path_gemm<3, 64,3,8>(W1,64,128,0,128, 12, sh_xf,sh_tf,sh_wb,tid,pair,g,oacc);
        path_gemm<3, 64,3,8>(W1,64,192,0,128, 21, sh_xf,sh_tf,sh_wb,tid,pair,g,oacc);
        path_gemm<3, 64,3,8>(W1,64,256,0,128, 30, sh_xf,sh_tf,sh_wb,tid,pair,g,oacc);
        path_gemm<5, 32,3,8>(W1,64,320,0,320, 39, sh_xf,sh_tf,sh_wb,tid,pair,g,oacc);
        path_gemm<5, 32,3,8>(W1,64,352,0,320, 54, sh_xf,sh_tf,sh_wb,tid,pair,g,oacc);
        store_chunk<3,8>(out,b0,128,0,pair,g,oacc);
    }
    // ---- l3 = 2: 32 cols, DK=5, CT=4, 1 chunk ----
    {
        zero_acc(oacc);
        path_gemm<1,128,5,4>(W2,32,  0,0,  0, 69, sh_xf,sh_tf,sh_wb,tid,pair,g,oacc);
        path_gemm<3, 64,5,4>(W2,32,128,0,128, 74, sh_xf,sh_tf,sh_wb,tid,pair,g,oacc);
        path_gemm<3, 64,5,4>(W2,32,192,0,128, 89, sh_xf,sh_tf,sh_wb,tid,pair,g,oacc);
        path_gemm<5, 32,5,4>(W2,32,256,0,320,104, sh_xf,sh_tf,sh_wb,tid,pair,g,oacc);
        path_gemm<5, 32,5,4>(W2,32,288,0,320,129, sh_xf,sh_tf,sh_wb,tid,pair,g,oacc);
        path_gemm<5, 32,5,4>(W2,32,320,0,320,154, sh_xf,sh_tf,sh_wb,tid,pair,g,oacc);
        store_chunk<5,4>(out,b0,320,0,pair,g,oacc);
    }
}

// ---------------------------------------------------------------------------
extern "C" void kernel_launch(void* const* d_in, const int* in_sizes, int n_in,
                              void* d_out, int out_size) {
    const float* x  = (const float*)d_in[0];
    const float* y  = (const float*)d_in[1];
    const float* W0 = (const float*)d_in[2];
    const float* W1 = (const float*)d_in[3];
    const float* W2 = (const float*)d_in[4];
    float* out = (float*)d_out;

    cudaFuncSetAttribute(tpl_kernel,
                         cudaFuncAttributeMaxDynamicSharedMemorySize,
                         (int)SMEM_BYTES);
    cg_init_kernel<<<15, 128>>>();
    tpl_kernel<<<16384 / TB, THREADS, SMEM_BYTES>>>(x, y, W0, W1, W2, out);
}